// round 6
// baseline (speedup 1.0000x reference)
#include <cuda_runtime.h>
#include <cuda_fp16.h>

#define NB    50
#define HID   32
#define HALFD 16
#define JJ    16         // HID/2 packed pairs
#define VSTH  17         // u32 stride per bucket row (odd -> <=2-way conflicts)
#define W2ST  17         // padded W2 row stride in smem
#define TPB   256
#define CR    4          // rows per thread per chunk
#define NCH   3          // chunks -> 12 rows/thread, 3072 rows/block

__device__ __forceinline__ unsigned long long pack2(float lo, float hi) {
    unsigned long long r;
    asm("mov.b64 %0, {%1, %2};" : "=l"(r) : "f"(lo), "f"(hi));
    return r;
}
__device__ __forceinline__ unsigned long long fma2(unsigned long long a,
                                                   unsigned long long b,
                                                   unsigned long long c) {
    unsigned long long d;
    asm("fma.rn.f32x2 %0, %1, %2, %3;" : "=l"(d) : "l"(a), "l"(b), "l"(c));
    return d;
}
__device__ __forceinline__ void unpack2(unsigned long long v, float& lo, float& hi) {
    asm("mov.b64 {%0, %1}, %2;" : "=f"(lo), "=f"(hi) : "l"(v));
}

__global__ __launch_bounds__(TPB, 5)
void lightwin_kernel(const float2* __restrict__ x, const int* __restrict__ buckets,
                     const float* __restrict__ W1, const float* __restrict__ b1,
                     const float* __restrict__ W2, const float* __restrict__ b2v,
                     const float* __restrict__ Wh, const float* __restrict__ bh,
                     float* __restrict__ out, int B) {
    __shared__ __align__(16) float sAB[HID * 2];     // W1 row0 | W1 row1
    __shared__ __align__(16) float sC[HID];          // b1
    __shared__ unsigned sVh[NB * VSTH];              // V = Wh @ W2^T, half2 pairs
    __shared__ float sc[NB];                         // c[b] = bh[b] + b2 . Wh[b]
    // staging for fused precompute (coalesced loads; bank-aware strides)
    __shared__ float sW2[HID * W2ST];
    __shared__ float sWh[NB * HALFD];
    __shared__ float sB2[HALFD];
    __shared__ float sBh[NB];

    int tid = threadIdx.x;

    // ---- stage 1: coalesced global -> smem
    if (tid < HID * 2)     sAB[tid] = W1[tid];
    if (tid < HID)         sC[tid]  = b1[tid];
    for (int i = tid; i < HID * HALFD; i += TPB)
        sW2[(i >> 4) * W2ST + (i & 15)] = W2[i];
    for (int i = tid; i < NB * HALFD; i += TPB)
        sWh[i] = Wh[i];
    if (tid < HALFD)       sB2[tid] = b2v[tid];
    if (tid < NB)          sBh[tid] = bh[tid];
    __syncthreads();

    // ---- stage 2: combined head weights V (half2) + folded bias c
    for (int e = tid; e < NB * JJ; e += TPB) {
        int b = e >> 4, jj = e & 15;
        const float* whp = &sWh[b * HALFD];
        const float* wa  = &sW2[(2 * jj)     * W2ST];
        const float* wb  = &sW2[(2 * jj + 1) * W2ST];
        float s0 = 0.f, s1 = 0.f;
        #pragma unroll
        for (int k = 0; k < HALFD; k++) {
            float wh = whp[k];
            s0 = fmaf(wa[k], wh, s0);
            s1 = fmaf(wb[k], wh, s1);
        }
        __half2 h = __floats2half2_rn(s0, s1);
        sVh[b * VSTH + jj] = *reinterpret_cast<unsigned*>(&h);
    }
    for (int b = tid; b < NB; b += TPB) {
        float s = sBh[b];
        #pragma unroll
        for (int k = 0; k < HALFD; k++)
            s = fmaf(sB2[k], sWh[b * HALFD + k], s);
        sc[b] = s;
    }
    __syncthreads();

    // ---- stage 3: main per-row work, 3 chunks of 4 rows/thread
    int blockBase = blockIdx.x * (TPB * CR * NCH) + tid;

    #pragma unroll 1
    for (int ch = 0; ch < NCH; ch++) {
        int base = blockBase + ch * (TPB * CR);

        unsigned long long x0d[CR], x1d[CR];
        float acc0[CR], acc1[CR];
        int   va[CR];

        #pragma unroll
        for (int r = 0; r < CR; r++) {
            int idx = base + r * TPB;
            bool p = idx < B;
            float2 xv = p ? __ldg(&x[idx]) : make_float2(0.f, 0.f);
            int b = p ? buckets[idx] : 0;
            b = ((unsigned)b < NB) ? b : (NB - 1);
            va[r]   = b * VSTH;
            x0d[r]  = pack2(xv.x, xv.x);
            x1d[r]  = pack2(xv.y, xv.y);
            acc0[r] = sc[b];           // head bias folded into accumulator
            acc1[r] = 0.f;
        }

        #pragma unroll
        for (int jj = 0; jj < JJ; jj++) {
            // warp-uniform weight pairs: broadcast LDS.64
            unsigned long long a2  = *(const unsigned long long*)&sAB[2 * jj];
            unsigned long long b2w = *(const unsigned long long*)&sAB[HID + 2 * jj];
            unsigned long long c2  = *(const unsigned long long*)&sC[2 * jj];
            #pragma unroll
            for (int r = 0; r < CR; r++) {
                unsigned long long z = fma2(x1d[r], b2w, c2);
                z = fma2(x0d[r], a2, z);
                float z0, z1;
                unpack2(z, z0, z1);
                float h0 = fmaxf(z0, 0.f);
                float h1 = fmaxf(z1, 0.f);
                unsigned vh = sVh[va[r] + jj];     // one LDS.32 = both fp16 weights
                float2 vf = __half22float2(*reinterpret_cast<__half2*>(&vh));
                acc0[r] = fmaf(h0, vf.x, acc0[r]);
                acc1[r] = fmaf(h1, vf.y, acc1[r]);
            }
        }

        #pragma unroll
        for (int r = 0; r < CR; r++) {
            int idx = base + r * TPB;
            if (idx < B) out[idx] = acc0[r] + acc1[r];
        }
    }
}

extern "C" void kernel_launch(void* const* d_in, const int* in_sizes, int n_in,
                              void* d_out, int out_size) {
    const float2* x     = (const float2*)d_in[0];
    const int* buckets  = (const int*)d_in[1];
    const float* W1     = (const float*)d_in[2];
    const float* b1     = (const float*)d_in[3];
    const float* W2     = (const float*)d_in[4];
    const float* b2v    = (const float*)d_in[5];
    const float* Wh     = (const float*)d_in[6];
    const float* bh     = (const float*)d_in[7];
    float* out          = (float*)d_out;

    int B = in_sizes[1];  // buckets element count = row count

    int rows_per_block = TPB * CR * NCH;              // 3072
    int grid = (B + rows_per_block - 1) / rows_per_block;  // 652 -> single wave @ 5 blocks/SM
    lightwin_kernel<<<grid, TPB>>>(x, buckets, W1, b1, W2, b2v, Wh, bh, out, B);
}

// round 9
// speedup vs baseline: 1.0199x; 1.0199x over previous
#include <cuda_runtime.h>
#include <cuda_fp16.h>

#define NB    50
#define HID   32
#define HALFD 16
#define JJ    16         // HID/2 packed pairs
#define VSTH  17         // u32 stride per bucket row (odd -> <=2-way conflicts)
#define W2ST  17         // padded W2 row stride in smem
#define TPB   256
#define RPT   8          // rows per thread

__device__ __forceinline__ unsigned long long pack2(float lo, float hi) {
    unsigned long long r;
    asm("mov.b64 %0, {%1, %2};" : "=l"(r) : "f"(lo), "f"(hi));
    return r;
}
__device__ __forceinline__ unsigned long long fma2(unsigned long long a,
                                                   unsigned long long b,
                                                   unsigned long long c) {
    unsigned long long d;
    asm("fma.rn.f32x2 %0, %1, %2, %3;" : "=l"(d) : "l"(a), "l"(b), "l"(c));
    return d;
}
__device__ __forceinline__ void unpack2(unsigned long long v, float& lo, float& hi) {
    asm("mov.b64 {%0, %1}, %2;" : "=f"(lo), "=f"(hi) : "l"(v));
}

__global__ __launch_bounds__(TPB, 4)
void lightwin_kernel(const float2* __restrict__ x, const int* __restrict__ buckets,
                     const float* __restrict__ W1, const float* __restrict__ b1,
                     const float* __restrict__ W2, const float* __restrict__ b2v,
                     const float* __restrict__ Wh, const float* __restrict__ bh,
                     float* __restrict__ out, int B) {
    __shared__ __align__(16) float sAB[HID * 2];     // W1 row0 | W1 row1
    __shared__ __align__(16) float sC[HID];          // b1
    __shared__ unsigned sVh[NB * VSTH];              // V = Wh @ W2^T, half2 pairs
    __shared__ float sc[NB];                         // c[b] = bh[b] + b2 . Wh[b]
    // staging for fused precompute (coalesced loads; bank-aware strides)
    __shared__ float sW2[HID * W2ST];
    __shared__ float sWh[NB * HALFD];
    __shared__ float sB2[HALFD];
    __shared__ float sBh[NB];

    int tid = threadIdx.x;

    // ---- stage 1: coalesced global -> smem
    if (tid < HID * 2)     sAB[tid] = W1[tid];
    if (tid < HID)         sC[tid]  = b1[tid];
    for (int i = tid; i < HID * HALFD; i += TPB)
        sW2[(i >> 4) * W2ST + (i & 15)] = W2[i];
    for (int i = tid; i < NB * HALFD; i += TPB)
        sWh[i] = Wh[i];
    if (tid < HALFD)       sB2[tid] = b2v[tid];
    if (tid < NB)          sBh[tid] = bh[tid];
    __syncthreads();

    // ---- stage 2: combined head weights V (half2) + folded bias c
    for (int e = tid; e < NB * JJ; e += TPB) {
        int b = e >> 4, jj = e & 15;
        const float* whp = &sWh[b * HALFD];
        const float* wa  = &sW2[(2 * jj)     * W2ST];
        const float* wb  = &sW2[(2 * jj + 1) * W2ST];
        float s0 = 0.f, s1 = 0.f;
        #pragma unroll
        for (int k = 0; k < HALFD; k++) {
            float wh = whp[k];
            s0 = fmaf(wa[k], wh, s0);
            s1 = fmaf(wb[k], wh, s1);
        }
        __half2 h = __floats2half2_rn(s0, s1);
        sVh[b * VSTH + jj] = *reinterpret_cast<unsigned*>(&h);
    }
    for (int b = tid; b < NB; b += TPB) {
        float s = sBh[b];
        #pragma unroll
        for (int k = 0; k < HALFD; k++)
            s = fmaf(sB2[k], sWh[b * HALFD + k], s);
        sc[b] = s;
    }
    __syncthreads();

    // ---- stage 3: main per-row loop (packed z + packed dot; scalar ReLU)
    int base = blockIdx.x * (TPB * RPT) + tid;

    unsigned long long x0d[RPT], x1d[RPT], accp[RPT];
    int va[RPT];

    #pragma unroll
    for (int r = 0; r < RPT; r++) {
        int idx = base + r * TPB;
        bool p = idx < B;
        float2 xv = p ? __ldg(&x[idx]) : make_float2(0.f, 0.f);
        int b = p ? buckets[idx] : 0;
        b = ((unsigned)b < NB) ? b : (NB - 1);
        va[r]   = b * VSTH;
        x0d[r]  = pack2(xv.x, xv.x);
        x1d[r]  = pack2(xv.y, xv.y);
        accp[r] = pack2(sc[b], 0.f);   // head bias folded into packed accumulator
    }

    #pragma unroll
    for (int jj = 0; jj < JJ; jj++) {
        // warp-uniform weight pairs: broadcast LDS.64
        unsigned long long a2  = *(const unsigned long long*)&sAB[2 * jj];
        unsigned long long b2w = *(const unsigned long long*)&sAB[HID + 2 * jj];
        unsigned long long c2  = *(const unsigned long long*)&sC[2 * jj];
        #pragma unroll
        for (int r = 0; r < RPT; r++) {
            unsigned long long z = fma2(x1d[r], b2w, c2);
            z = fma2(x0d[r], a2, z);
            float z0, z1;
            unpack2(z, z0, z1);                     // reg-pair rename (no SASS)
            float h0 = fmaxf(z0, 0.f);
            float h1 = fmaxf(z1, 0.f);
            unsigned vh = sVh[va[r] + jj];          // one LDS.32 = both fp16 weights
            float2 vf = __half22float2(*reinterpret_cast<__half2*>(&vh));
            // packed dot-accumulate: one FFMA2 instead of two FFMA
            accp[r] = fma2(pack2(h0, h1), pack2(vf.x, vf.y), accp[r]);
        }
    }

    #pragma unroll
    for (int r = 0; r < RPT; r++) {
        int idx = base + r * TPB;
        float alo, ahi;
        unpack2(accp[r], alo, ahi);
        if (idx < B) out[idx] = alo + ahi;
    }
}

extern "C" void kernel_launch(void* const* d_in, const int* in_sizes, int n_in,
                              void* d_out, int out_size) {
    const float2* x     = (const float2*)d_in[0];
    const int* buckets  = (const int*)d_in[1];
    const float* W1     = (const float*)d_in[2];
    const float* b1     = (const float*)d_in[3];
    const float* W2     = (const float*)d_in[4];
    const float* b2v    = (const float*)d_in[5];
    const float* Wh     = (const float*)d_in[6];
    const float* bh     = (const float*)d_in[7];
    float* out          = (float*)d_out;

    int B = in_sizes[1];  // buckets element count = row count

    int rows_per_block = TPB * RPT;
    int grid = (B + rows_per_block - 1) / rows_per_block;   // 977
    lightwin_kernel<<<grid, TPB>>>(x, buckets, W1, b1, W2, b2v, Wh, bh, out, B);
}

// round 10
// speedup vs baseline: 1.0994x; 1.0780x over previous
#include <cuda_runtime.h>
#include <cuda_fp16.h>

#define NB    50
#define HID   32
#define HALFD 16
#define JJ    16         // HID/2 packed pairs
#define VSTH  17         // u32 stride per bucket row (odd -> <=2-way conflicts)
#define W2ST  17         // padded W2 row stride in smem
#define TPB   256
#define CR    4          // rows per thread per chunk
#define CHROWS (TPB * CR)   // 1024 rows per chunk
#define NBLK  740        // 148 SMs x 5 blocks -> persistent, exactly resident

__device__ __forceinline__ unsigned long long pack2(float lo, float hi) {
    unsigned long long r;
    asm("mov.b64 %0, {%1, %2};" : "=l"(r) : "f"(lo), "f"(hi));
    return r;
}
__device__ __forceinline__ unsigned long long fma2(unsigned long long a,
                                                   unsigned long long b,
                                                   unsigned long long c) {
    unsigned long long d;
    asm("fma.rn.f32x2 %0, %1, %2, %3;" : "=l"(d) : "l"(a), "l"(b), "l"(c));
    return d;
}
__device__ __forceinline__ void unpack2(unsigned long long v, float& lo, float& hi) {
    asm("mov.b64 {%0, %1}, %2;" : "=f"(lo), "=f"(hi) : "l"(v));
}

__global__ __launch_bounds__(TPB, 5)
void lightwin_kernel(const float2* __restrict__ x, const int* __restrict__ buckets,
                     const float* __restrict__ W1, const float* __restrict__ b1,
                     const float* __restrict__ W2, const float* __restrict__ b2v,
                     const float* __restrict__ Wh, const float* __restrict__ bh,
                     float* __restrict__ out, int B, int nchunks) {
    __shared__ __align__(16) float sAB[HID * 2];     // W1 row0 | W1 row1
    __shared__ __align__(16) float sC[HID];          // b1
    __shared__ unsigned sVh[NB * VSTH];              // V = Wh @ W2^T, half2 pairs
    __shared__ float sc[NB];                         // c[b] = bh[b] + b2 . Wh[b]
    // staging for fused precompute (coalesced loads; bank-aware strides)
    __shared__ float sW2[HID * W2ST];
    __shared__ float sWh[NB * HALFD];
    __shared__ float sB2[HALFD];
    __shared__ float sBh[NB];

    int tid = threadIdx.x;

    // ---- stage 1: coalesced global -> smem (paid once per persistent block)
    if (tid < HID * 2)     sAB[tid] = W1[tid];
    if (tid < HID)         sC[tid]  = b1[tid];
    for (int i = tid; i < HID * HALFD; i += TPB)
        sW2[(i >> 4) * W2ST + (i & 15)] = W2[i];
    for (int i = tid; i < NB * HALFD; i += TPB)
        sWh[i] = Wh[i];
    if (tid < HALFD)       sB2[tid] = b2v[tid];
    if (tid < NB)          sBh[tid] = bh[tid];
    __syncthreads();

    // ---- stage 2: combined head weights V (half2) + folded bias c
    for (int e = tid; e < NB * JJ; e += TPB) {
        int b = e >> 4, jj = e & 15;
        const float* whp = &sWh[b * HALFD];
        const float* wa  = &sW2[(2 * jj)     * W2ST];
        const float* wb  = &sW2[(2 * jj + 1) * W2ST];
        float s0 = 0.f, s1 = 0.f;
        #pragma unroll
        for (int k = 0; k < HALFD; k++) {
            float wh = whp[k];
            s0 = fmaf(wa[k], wh, s0);
            s1 = fmaf(wb[k], wh, s1);
        }
        __half2 h = __floats2half2_rn(s0, s1);
        sVh[b * VSTH + jj] = *reinterpret_cast<unsigned*>(&h);
    }
    for (int b = tid; b < NB; b += TPB) {
        float s = sBh[b];
        #pragma unroll
        for (int k = 0; k < HALFD; k++)
            s = fmaf(sB2[k], sWh[b * HALFD + k], s);
        sc[b] = s;
    }
    __syncthreads();

    // ---- stage 3: persistent block-stride loop over 1024-row chunks
    for (int ch = blockIdx.x; ch < nchunks; ch += NBLK) {
        int base = ch * CHROWS + tid;

        unsigned long long x0d[CR], x1d[CR];
        float acc0[CR], acc1[CR];
        int   va[CR];

        #pragma unroll
        for (int r = 0; r < CR; r++) {
            int idx = base + r * TPB;
            bool p = idx < B;
            float2 xv = p ? __ldg(&x[idx]) : make_float2(0.f, 0.f);
            int b = p ? buckets[idx] : 0;
            b = ((unsigned)b < NB) ? b : (NB - 1);
            va[r]   = b * VSTH;
            x0d[r]  = pack2(xv.x, xv.x);
            x1d[r]  = pack2(xv.y, xv.y);
            acc0[r] = sc[b];           // head bias folded into accumulator
            acc1[r] = 0.f;
        }

        #pragma unroll
        for (int jj = 0; jj < JJ; jj++) {
            // warp-uniform weight pairs: broadcast LDS.64
            unsigned long long a2  = *(const unsigned long long*)&sAB[2 * jj];
            unsigned long long b2w = *(const unsigned long long*)&sAB[HID + 2 * jj];
            unsigned long long c2  = *(const unsigned long long*)&sC[2 * jj];
            #pragma unroll
            for (int r = 0; r < CR; r++) {
                unsigned long long z = fma2(x1d[r], b2w, c2);
                z = fma2(x0d[r], a2, z);
                float z0, z1;
                unpack2(z, z0, z1);
                float h0 = fmaxf(z0, 0.f);
                float h1 = fmaxf(z1, 0.f);
                unsigned vh = sVh[va[r] + jj];     // one LDS.32 = both fp16 weights
                float2 vf = __half22float2(*reinterpret_cast<__half2*>(&vh));
                acc0[r] = fmaf(h0, vf.x, acc0[r]);
                acc1[r] = fmaf(h1, vf.y, acc1[r]);
            }
        }

        #pragma unroll
        for (int r = 0; r < CR; r++) {
            int idx = base + r * TPB;
            if (idx < B) out[idx] = acc0[r] + acc1[r];
        }
    }
}

extern "C" void kernel_launch(void* const* d_in, const int* in_sizes, int n_in,
                              void* d_out, int out_size) {
    const float2* x     = (const float2*)d_in[0];
    const int* buckets  = (const int*)d_in[1];
    const float* W1     = (const float*)d_in[2];
    const float* b1     = (const float*)d_in[3];
    const float* W2     = (const float*)d_in[4];
    const float* b2v    = (const float*)d_in[5];
    const float* Wh     = (const float*)d_in[6];
    const float* bh     = (const float*)d_in[7];
    float* out          = (float*)d_out;

    int B = in_sizes[1];  // buckets element count = row count
    int nchunks = (B + CHROWS - 1) / CHROWS;   // 1954
    int grid = NBLK < nchunks ? NBLK : nchunks;
    lightwin_kernel<<<grid, TPB>>>(x, buckets, W1, b1, W2, b2v, Wh, bh, out, B, nchunks);
}